// round 6
// baseline (speedup 1.0000x reference)
#include <cuda_runtime.h>
#include <cuda_bf16.h>
#include <cstdint>

#define ND 768
#define SZ (768*768)
#define MNTOT SZ
typedef long long ll;

// ---------------- scratch (device globals) ----------------------------------
__device__ float g_Tf[10*SZ];                         // fp32 T[side][k]
__device__ __align__(16) __nv_bfloat16 g_Tsh[10*SZ];  // split hi
__device__ __align__(16) __nv_bfloat16 g_Tsl[10*SZ];  // split lo
__device__ __align__(16) __nv_bfloat16 g_xTh[SZ];
__device__ __align__(16) __nv_bfloat16 g_xTl[SZ];
__device__ float g_Yf[4*SZ];                          // Y_1..Y_4 fp32
__device__ __align__(16) __nv_bfloat16 g_Ysh[5*SZ];   // slot0 = x split
__device__ __align__(16) __nv_bfloat16 g_Ysl[5*SZ];
__device__ float g_bff[20*SZ];
__device__ __align__(16) __nv_bfloat16 g_hh[32*SZ];   // h split hi
__device__ __align__(16) __nv_bfloat16 g_hl[32*SZ];   // h split lo
__device__ float g_c[32*SZ];

struct SrcPtrs { const float* p[25]; };

// ---------------- helpers -----------------------------------------------------
#define SWZ(x) ((x) ^ (((x) >> 3) & 0x70))

__device__ __forceinline__ uint32_t smem_u32(const void* p) {
  uint32_t a;
  asm("{ .reg .u64 t; cvta.to.shared.u64 t, %1; cvt.u32.u64 %0, t; }"
      : "=r"(a) : "l"(p));
  return a;
}

__device__ __forceinline__ void cpa16(uint32_t dst, const void* src) {
  asm volatile("cp.async.cg.shared.global [%0], [%1], 16;"
               :: "r"(dst), "l"(src) : "memory");
}
#define CP_COMMIT() asm volatile("cp.async.commit_group;" ::: "memory")
#define CP_WAIT(n)  asm volatile("cp.async.wait_group %0;" :: "n"(n) : "memory")

__device__ __forceinline__ void ldm4(uint32_t* r, uint32_t addr) {
  asm volatile("ldmatrix.sync.aligned.m8n8.x4.shared.b16 {%0,%1,%2,%3}, [%4];"
               : "=r"(r[0]), "=r"(r[1]), "=r"(r[2]), "=r"(r[3]) : "r"(addr));
}

__device__ __forceinline__ void mma16816(float* c, const uint32_t* a,
                                         const uint32_t* b) {
  asm volatile(
      "mma.sync.aligned.m16n8k16.row.col.f32.bf16.bf16.f32 "
      "{%0,%1,%2,%3},{%4,%5,%6,%7},{%8,%9},{%0,%1,%2,%3};"
      : "+f"(c[0]), "+f"(c[1]), "+f"(c[2]), "+f"(c[3])
      : "r"(a[0]), "r"(a[1]), "r"(a[2]), "r"(a[3]), "r"(b[0]), "r"(b[1]));
}

__device__ __forceinline__ uint32_t pack2(__nv_bfloat16 a, __nv_bfloat16 b) {
  __nv_bfloat162 t(a, b);
  return *reinterpret_cast<uint32_t*>(&t);
}

// load one 64-wide K chunk of 4 matrices (Ah[64],Al[64],Bh[128],Bl[128])
__device__ __forceinline__ void load_chunk(
    uint32_t sb, int s, int kc, int tid, int brow, int bcol,
    const __nv_bfloat16* a0, const __nv_bfloat16* a1,
    const __nv_bfloat16* b0, const __nv_bfloat16* b1)
{
  constexpr int ASTAGE = 64 * 128;             // 8 KB
  constexpr int STAGE  = 2 * ASTAGE + 32768;   // 48 KB
#pragma unroll
  for (int i = 0; i < 12; i++) {
    int idx = tid + i * 256;
    int c4 = idx & 7;
    int rowIdx = idx >> 3;
    const __nv_bfloat16* src;
    uint32_t dstbase;
    if (rowIdx < 128) {                 // uniform per i
      int mat = rowIdx >> 6;
      int row = rowIdx & 63;
      src = (mat ? a1 : a0) + (ll)(brow + row) * ND + kc * 64 + c4 * 8;
      dstbase = mat * ASTAGE + SWZ(row * 128 + c4 * 16);
    } else {
      int rr = rowIdx - 128;
      int mat = rr >> 7;
      int row = rr & 127;
      src = (mat ? b1 : b0) + (ll)(bcol + row) * ND + kc * 64 + c4 * 8;
      dstbase = 2 * ASTAGE + mat * 16384 + SWZ(row * 128 + c4 * 16);
    }
    cpa16(sb + s * STAGE + dstbase, src);
  }
}

// ---------------- tensor-core GEMM: C = alpha*A@B~^T + beta*Cin --------------
// 64x128 tile, 3-stage cp.async, 1 sync per chunk (round-4 best config).
__global__ __launch_bounds__(256, 1) void tc_gemm(
    const __nv_bfloat16* __restrict__ Ah, const __nv_bfloat16* __restrict__ Al,
    const __nv_bfloat16* __restrict__ Bh, const __nv_bfloat16* __restrict__ Bl,
    const float* __restrict__ Cin, float* __restrict__ Cout,
    __nv_bfloat16* __restrict__ Couth, __nv_bfloat16* __restrict__ Coutl,
    ll sAz, ll sAdiv, int adiv,
    ll sBz, ll sBmod, int bmod,
    ll sCinz, ll sCz, float alpha, float beta, int cinmode)
{
  extern __shared__ char dsm[];
  constexpr int ASTAGE = 64 * 128;
  constexpr int STAGE  = 2 * ASTAGE + 32768;

  int z = blockIdx.z;
  ll offA = sAz * z + sAdiv * (z / adiv);
  ll offB = sBz * z + sBmod * (z % bmod);
  const __nv_bfloat16* ah = Ah + offA;
  const __nv_bfloat16* al = Al + offA;
  const __nv_bfloat16* bh = Bh + offB;
  const __nv_bfloat16* bl = Bl + offB;
  const int brow = blockIdx.y * 64;
  const int bcol = blockIdx.x * 128;

  int tid = threadIdx.x;
  int lane = tid & 31;
  int wid = tid >> 5;
  int wrow = (wid & 1) * 32;
  int wcol = (wid >> 1) * 32;

  uint32_t raw = smem_u32(dsm);
  uint32_t sb = (raw + 1023) & ~1023u;

  float acc[2][4][4];
#pragma unroll
  for (int mi = 0; mi < 2; mi++)
#pragma unroll
    for (int ni = 0; ni < 4; ni++)
#pragma unroll
      for (int e = 0; e < 4; e++) acc[mi][ni][e] = 0.0f;

  int a_r  = (lane & 7) + ((lane >> 3) & 1) * 8;
  int a_k8 = ((lane >> 4) & 1) * 8;
  int b_r  = (lane & 7) + ((lane >> 4) & 1) * 8;
  int b_k8 = ((lane >> 3) & 1) * 8;

  load_chunk(sb, 0, 0, tid, brow, bcol, ah, al, bh, bl); CP_COMMIT();
  load_chunk(sb, 1, 1, tid, brow, bcol, ah, al, bh, bl); CP_COMMIT();

  for (int kc = 0; kc < 12; kc++) {
    if (kc < 11) { CP_WAIT(1); } else { CP_WAIT(0); }
    __syncthreads();

    uint32_t st  = sb + (kc % 3) * STAGE;
    uint32_t tAh = st;
    uint32_t tAl = st + ASTAGE;
    uint32_t tBh = st + 2 * ASTAGE;
    uint32_t tBl = tBh + 16384;

#pragma unroll
    for (int s = 0; s < 4; s++) {
      uint32_t fah[2][4], fal[2][4];
#pragma unroll
      for (int mi = 0; mi < 2; mi++) {
        int r = wrow + mi * 16 + a_r;
        uint32_t off = SWZ(r * 128 + (s * 16 + a_k8) * 2);
        ldm4(fah[mi], tAh + off);
        ldm4(fal[mi], tAl + off);
      }
      uint32_t fbh[4][2], fbl[4][2];
#pragma unroll
      for (int nj = 0; nj < 2; nj++) {
        int r = wcol + nj * 16 + b_r;
        uint32_t off = SWZ(r * 128 + (s * 16 + b_k8) * 2);
        uint32_t t4[4];
        ldm4(t4, tBh + off);
        fbh[nj * 2][0] = t4[0]; fbh[nj * 2][1] = t4[1];
        fbh[nj * 2 + 1][0] = t4[2]; fbh[nj * 2 + 1][1] = t4[3];
        ldm4(t4, tBl + off);
        fbl[nj * 2][0] = t4[0]; fbl[nj * 2][1] = t4[1];
        fbl[nj * 2 + 1][0] = t4[2]; fbl[nj * 2 + 1][1] = t4[3];
      }
#pragma unroll
      for (int mi = 0; mi < 2; mi++)
#pragma unroll
        for (int ni = 0; ni < 4; ni++)
          mma16816(acc[mi][ni], fah[mi], fbh[ni]);
#pragma unroll
      for (int mi = 0; mi < 2; mi++)
#pragma unroll
        for (int ni = 0; ni < 4; ni++)
          mma16816(acc[mi][ni], fah[mi], fbl[ni]);
#pragma unroll
      for (int mi = 0; mi < 2; mi++)
#pragma unroll
        for (int ni = 0; ni < 4; ni++)
          mma16816(acc[mi][ni], fal[mi], fbh[ni]);
    }

    if (kc + 2 < 12) {
      load_chunk(sb, (kc + 2) % 3, kc + 2, tid, brow, bcol, ah, al, bh, bl);
      CP_COMMIT();
    }
  }

  // ---- epilogue: registers -> gmem (fp32 + optional split bf16) -------------
  const float* cinp = (cinmode == 2) ? (Cin + sCinz * z) : (const float*)0;
  float* co = Cout + sCz * z;
  __nv_bfloat16* coh = Couth ? (Couth + sCz * z) : (__nv_bfloat16*)0;
  __nv_bfloat16* col = Coutl ? (Coutl + sCz * z) : (__nv_bfloat16*)0;
  int qr = lane >> 2, qc = lane & 3;

#pragma unroll
  for (int mi = 0; mi < 2; mi++) {
#pragma unroll
    for (int ni = 0; ni < 4; ni++) {
      int gr0 = brow + wrow + mi * 16 + qr;
      int gc  = bcol + wcol + ni * 8 + qc * 2;
      float2 v0, v1;
      v0.x = alpha * acc[mi][ni][0];
      v0.y = alpha * acc[mi][ni][1];
      v1.x = alpha * acc[mi][ni][2];
      v1.y = alpha * acc[mi][ni][3];
      if (cinmode == 2) {
        float2 c0 = *(const float2*)&cinp[(ll)gr0 * ND + gc];
        float2 c1 = *(const float2*)&cinp[(ll)(gr0 + 8) * ND + gc];
        v0.x += beta * c0.x; v0.y += beta * c0.y;
        v1.x += beta * c1.x; v1.y += beta * c1.y;
      } else if (cinmode == 1) {
        if (gr0 == gc)         v0.x += beta;
        if (gr0 == gc + 1)     v0.y += beta;
        if (gr0 + 8 == gc)     v1.x += beta;
        if (gr0 + 8 == gc + 1) v1.y += beta;
      }
      *(float2*)&co[(ll)gr0 * ND + gc]       = v0;
      *(float2*)&co[(ll)(gr0 + 8) * ND + gc] = v1;
      if (coh) {
        __nv_bfloat16 h0 = __float2bfloat16(v0.x);
        __nv_bfloat16 h1 = __float2bfloat16(v0.y);
        __nv_bfloat16 h2 = __float2bfloat16(v1.x);
        __nv_bfloat16 h3 = __float2bfloat16(v1.y);
        *(uint32_t*)&coh[(ll)gr0 * ND + gc]       = pack2(h0, h1);
        *(uint32_t*)&coh[(ll)(gr0 + 8) * ND + gc] = pack2(h2, h3);
        *(uint32_t*)&col[(ll)gr0 * ND + gc] =
            pack2(__float2bfloat16(v0.x - __bfloat162float(h0)),
                  __float2bfloat16(v0.y - __bfloat162float(h1)));
        *(uint32_t*)&col[(ll)(gr0 + 8) * ND + gc] =
            pack2(__float2bfloat16(v1.x - __bfloat162float(h2)),
                  __float2bfloat16(v1.y - __bfloat162float(h3)));
      }
    }
  }
}

// ---------------- fp32 -> split bf16 (setup only) ----------------------------
__global__ __launch_bounds__(256) void split_kernel(
    const float* __restrict__ src, __nv_bfloat16* __restrict__ hi,
    __nv_bfloat16* __restrict__ lo, ll sS, ll sD)
{
  ll so = sS * blockIdx.z, dofs = sD * blockIdx.z;
  int idx = blockIdx.x * 256 + threadIdx.x;
  float4 v = *(const float4*)(src + so + (ll)idx * 4);
  float a[4] = {v.x, v.y, v.z, v.w};
  __nv_bfloat16 h[4], l[4];
#pragma unroll
  for (int e = 0; e < 4; e++) {
    h[e] = __float2bfloat16(a[e]);
    l[e] = __float2bfloat16(a[e] - __bfloat162float(h[e]));
  }
  uint2 uh, ul;
  uh.x = pack2(h[0], h[1]); uh.y = pack2(h[2], h[3]);
  ul.x = pack2(l[0], l[1]); ul.y = pack2(l[2], l[3]);
  *(uint2*)(hi + dofs + (ll)idx * 4) = uh;
  *(uint2*)(lo + dofs + (ll)idx * 4) = ul;
}

// ---------------- transpose + split: xT = x^T --------------------------------
__global__ void tsplit_kernel(const float* __restrict__ src,
                              __nv_bfloat16* __restrict__ th,
                              __nv_bfloat16* __restrict__ tl)
{
  __shared__ float t[32][33];
  int bx = blockIdx.x * 32, by = blockIdx.y * 32;
  int tx = threadIdx.x, ty = threadIdx.y;
#pragma unroll
  for (int i = 0; i < 4; i++)
    t[ty + 8 * i][tx] = src[(ll)(by + ty + 8 * i) * ND + bx + tx];
  __syncthreads();
#pragma unroll
  for (int i = 0; i < 4; i++) {
    float a = t[tx][ty + 8 * i];
    __nv_bfloat16 h = __float2bfloat16(a);
    __nv_bfloat16 l = __float2bfloat16(a - __bfloat162float(h));
    ll o = (ll)(bx + ty + 8 * i) * ND + by + tx;
    th[o] = h;
    tl[o] = l;
  }
}

// ---------------- fused conv-combine + HMMA gates + dx + x-split -------------
// smem (from 1024-aligned base):
//   [0,16K)   AH: [128 pts][64 k] bf16 hi   (k 0-31 = xc, 32-63 = h)
//   [16K,32K) AL: lo
//   [32K,48K) WH: [128 n][64 k] bf16 hi     (n = gate*32+o; k<32 W, k>=32 U)
//   [48K,64K) WL: lo
//   PRE overlays [0,64K): [128 n][128 r] fp32, 512B rows (after sync)
//   [64K+..)  scalars: th 800f, bs 32f, swo 32f, sbg 128f, sdx 256f
__device__ __forceinline__ float sigf(float v) {
  return __fdividef(1.0f, 1.0f + __expf(-v));
}

__global__ __launch_bounds__(256) void fused_rnn(
    SrcPtrs srcs, const float* __restrict__ theta, const float* __restrict__ bias,
    const float* __restrict__ Wf, const float* __restrict__ Uf, const float* __restrict__ bf_,
    const float* __restrict__ Wi, const float* __restrict__ Ui, const float* __restrict__ bi_,
    const float* __restrict__ Wo, const float* __restrict__ Uo, const float* __restrict__ bo_,
    const float* __restrict__ Wc, const float* __restrict__ Uc, const float* __restrict__ bc_,
    const float* __restrict__ Wout, const float* __restrict__ bout,
    float* c, __nv_bfloat16* hh_g, __nv_bfloat16* hl_g, float* x,
    __nv_bfloat16* __restrict__ xsh, __nv_bfloat16* __restrict__ xsl,
    int first, int last)
{
  extern __shared__ char dsm[];
  uint32_t raw = smem_u32(dsm);
  uint32_t sb = (raw + 1023) & ~1023u;
  char* base = dsm + (sb - raw);

  float* th  = (float*)(base + 65536);            // 800
  float* bs  = (float*)(base + 65536 + 3200);     // 32
  float* swo = (float*)(base + 65536 + 3328);     // 32
  float* sbg = (float*)(base + 65536 + 3456);     // 128
  float* sdx = (float*)(base + 65536 + 3968);     // 256

  int t = threadIdx.x;
  int lane = t & 31;
  int w = t >> 5;

  // ---- phase 0: scalars + split W/U into WH/WL -------------------------------
  for (int i = t; i < 800; i += 256) th[i] = theta[i];
  if (t < 32) { bs[t] = bias[t]; swo[t] = Wout[t]; }
  if (t < 128) { const float* bx[4] = {bf_, bi_, bo_, bc_}; sbg[t] = bx[t >> 5][t & 31]; }
  {
    const float* Ws[4] = {Wf, Wi, Wo, Wc};
    const float* Us[4] = {Uf, Ui, Uo, Uc};
    for (int idx = t; idx < 8192; idx += 256) {
      int n = idx >> 6, k = idx & 63;
      int g = n >> 5, o = n & 31;
      float v = (k < 32) ? Ws[g][k * 32 + o] : Us[g][(k - 32) * 32 + o];
      __nv_bfloat16 vh = __float2bfloat16(v);
      __nv_bfloat16 vl = __float2bfloat16(v - __bfloat162float(vh));
      uint32_t byte = n * 128 + k * 2;
      *(__nv_bfloat16*)(base + 32768 + SWZ(byte)) = vh;
      *(__nv_bfloat16*)(base + 49152 + SWZ(byte)) = vl;
    }
  }

  // ---- phase 1.5: h -> A cols 32..63 (bf16 hi/lo; zeros on first iter) ------
#pragma unroll 4
  for (int i = 0; i < 16; i++) {
    int idx = t + i * 256;
    int r2 = idx & 127;
    int k = idx >> 7;
    uint32_t byte = r2 * 128 + 64 + k * 2;
    __nv_bfloat16 vh, vl;
    if (first) {
      vh = __float2bfloat16(0.0f); vl = vh;
    } else {
      size_t gi = (size_t)k * MNTOT + (size_t)blockIdx.x * 128 + r2;
      vh = hh_g[gi]; vl = hl_g[gi];
    }
    *(__nv_bfloat16*)(base + SWZ(byte)) = vh;
    *(__nv_bfloat16*)(base + 16384 + SWZ(byte)) = vl;
  }
  __syncthreads();   // th/bs ready for phase 1

  // ---- phase 1: conv combine -> A cols 0..31 (xc split) ----------------------
  {
    int r  = t & 127;
    int oh = (t >> 7) * 16;
    size_t rg = (size_t)blockIdx.x * 128 + r;
    float out[16];
#pragma unroll
    for (int o = 0; o < 16; o++) out[o] = bs[oh + o];
#pragma unroll
    for (int ij = 0; ij < 25; ij++) {
      float v = __ldg(srcs.p[ij] + rg);
      const float* tw = &th[ij * 32 + oh];
#pragma unroll
      for (int o = 0; o < 16; o++) out[o] += v * tw[o];
    }
#pragma unroll
    for (int i = 0; i < 8; i++) {
      float a0 = out[2 * i], a1 = out[2 * i + 1];
      __nv_bfloat16 h0 = __float2bfloat16(a0);
      __nv_bfloat16 h1 = __float2bfloat16(a1);
      uint32_t byte = r * 128 + (oh + 2 * i) * 2;
      *(uint32_t*)(base + SWZ(byte)) = pack2(h0, h1);
      *(uint32_t*)(base + 16384 + SWZ(byte)) =
          pack2(__float2bfloat16(a0 - __bfloat162float(h0)),
                __float2bfloat16(a1 - __bfloat162float(h1)));
    }
  }
  __syncthreads();

  // ---- phase 2: preact = [xc|h] @ [[W];[U]]  (3-term split-bf16 HMMA) -------
  int a_r  = (lane & 7) + ((lane >> 3) & 1) * 8;
  int a_k8 = ((lane >> 4) & 1) * 8;
  int b_r  = (lane & 7) + ((lane >> 4) & 1) * 8;
  int b_k8 = ((lane >> 3) & 1) * 8;

  float acc[16][4];
#pragma unroll
  for (int nt = 0; nt < 16; nt++)
#pragma unroll
    for (int e = 0; e < 4; e++) acc[nt][e] = 0.0f;

#pragma unroll
  for (int ks = 0; ks < 4; ks++) {
    uint32_t abyte = SWZ((w * 16 + a_r) * 128 + (ks * 16 + a_k8) * 2);
    uint32_t ah4[4], al4[4];
    ldm4(ah4, sb + abyte);
    ldm4(al4, sb + 16384 + abyte);
#pragma unroll
    for (int np = 0; np < 8; np++) {
      uint32_t bbyte = SWZ((np * 16 + b_r) * 128 + (ks * 16 + b_k8) * 2);
      uint32_t bh4[4], bl4[4];
      ldm4(bh4, sb + 32768 + bbyte);
      ldm4(bl4, sb + 49152 + bbyte);
      mma16816(acc[2 * np],     ah4, bh4);
      mma16816(acc[2 * np + 1], ah4, bh4 + 2);
      mma16816(acc[2 * np],     ah4, bl4);
      mma16816(acc[2 * np + 1], ah4, bl4 + 2);
      mma16816(acc[2 * np],     al4, bh4);
      mma16816(acc[2 * np + 1], al4, bh4 + 2);
    }
  }
  __syncthreads();   // all mma reads of A/W done -> safe to overlay with PRE

  // ---- stage PRE[n][r] fp32 (overlays tiles) ---------------------------------
  {
    int qr = lane >> 2, qc = lane & 3;
    int r0 = w * 16 + qr;
#pragma unroll
    for (int nt = 0; nt < 16; nt++) {
      int n0 = nt * 8 + qc * 2;
      *(float*)(base + (uint32_t)n0 * 512 + r0 * 4)             = acc[nt][0];
      *(float*)(base + (uint32_t)(n0 + 1) * 512 + r0 * 4)       = acc[nt][1];
      *(float*)(base + (uint32_t)n0 * 512 + (r0 + 8) * 4)       = acc[nt][2];
      *(float*)(base + (uint32_t)(n0 + 1) * 512 + (r0 + 8) * 4) = acc[nt][3];
    }
  }
  __syncthreads();

  // ---- phase 3: gates, c/h update, dx partials -------------------------------
  {
    int r  = t & 127;
    int oh = (t >> 7) * 16;
    size_t pt = (size_t)blockIdx.x * 128 + r;
    float pd = 0.0f;
#pragma unroll
    for (int i = 0; i < 16; i++) {
      int oo = oh + i;
      float zf = *(float*)(base + (uint32_t)oo * 512 + r * 4)         + sbg[oo];
      float zi = *(float*)(base + (uint32_t)(32 + oo) * 512 + r * 4)  + sbg[32 + oo];
      float zo = *(float*)(base + (uint32_t)(64 + oo) * 512 + r * 4)  + sbg[64 + oo];
      float zc = *(float*)(base + (uint32_t)(96 + oo) * 512 + r * 4)  + sbg[96 + oo];
      float ig = sigf(zi), cu = sigf(zc);
      float cnew = ig * cu;
      if (!first) cnew += sigf(zf) * c[(size_t)oo * MNTOT + pt];
      pd += cnew * swo[oo];
      if (!last) {
        c[(size_t)oo * MNTOT + pt] = cnew;
        float hv = sigf(zo) * sigf(cnew);
        __nv_bfloat16 hvh = __float2bfloat16(hv);
        hh_g[(size_t)oo * MNTOT + pt] = hvh;
        hl_g[(size_t)oo * MNTOT + pt] =
            __float2bfloat16(hv - __bfloat162float(hvh));
      }
    }
    sdx[r + 128 * (t >> 7)] = pd;
  }
  __syncthreads();

  if (t < 128) {
    float s = __ldg(bout) + sdx[t] + sdx[t + 128];
    size_t gi = (size_t)blockIdx.x * 128 + t;
    float xn = x[gi] + tanhf(s);
    x[gi] = xn;
    if (!last) {
      __nv_bfloat16 xh2 = __float2bfloat16(xn);
      xsh[gi] = xh2;
      xsl[gi] = __float2bfloat16(xn - __bfloat162float(xh2));
    }
  }
}

// ---------------- orchestration ----------------------------------------------
extern "C" void kernel_launch(void* const* d_in, const int* in_sizes, int n_in,
                              void* d_out, int out_size)
{
  const float* x     = (const float*)d_in[0];
  const float* L_row = (const float*)d_in[1];
  const float* L_col = (const float*)d_in[2];
  const float* theta = (const float*)d_in[3];
  const float* bias  = (const float*)d_in[4];
  const float* W_f = (const float*)d_in[5];
  const float* U_f = (const float*)d_in[6];
  const float* b_f = (const float*)d_in[7];
  const float* W_i = (const float*)d_in[8];
  const float* U_i = (const float*)d_in[9];
  const float* b_i = (const float*)d_in[10];
  const float* W_o = (const float*)d_in[11];
  const float* U_o = (const float*)d_in[12];
  const float* b_o = (const float*)d_in[13];
  const float* W_c = (const float*)d_in[14];
  const float* U_c = (const float*)d_in[15];
  const float* b_c = (const float*)d_in[16];
  const float* W_out = (const float*)d_in[17];
  const float* b_out = (const float*)d_in[18];
  // d_in[19] = nb_iterations_rnn = 3 (fixed by setup)

  float* xcur = (float*)d_out;

  float *Tf, *Yf, *bff, *c;
  __nv_bfloat16 *Tsh, *Tsl, *xTh, *xTl, *Ysh, *Ysl, *hh, *hl;
  cudaGetSymbolAddress((void**)&Tf,  g_Tf);
  cudaGetSymbolAddress((void**)&Tsh, g_Tsh);
  cudaGetSymbolAddress((void**)&Tsl, g_Tsl);
  cudaGetSymbolAddress((void**)&xTh, g_xTh);
  cudaGetSymbolAddress((void**)&xTl, g_xTl);
  cudaGetSymbolAddress((void**)&Yf,  g_Yf);
  cudaGetSymbolAddress((void**)&Ysh, g_Ysh);
  cudaGetSymbolAddress((void**)&Ysl, g_Ysl);
  cudaGetSymbolAddress((void**)&bff, g_bff);
  cudaGetSymbolAddress((void**)&hh,  g_hh);
  cudaGetSymbolAddress((void**)&hl,  g_hl);
  cudaGetSymbolAddress((void**)&c,   g_c);

  const ll S = SZ;
  const int DSM = 1024 + 3 * 49152;            // 3-stage 48KB pipeline
  const int FSM = 1024 + 65536 + 3968 + 1024;  // tiles/PRE + scalars + sdx
  cudaFuncSetAttribute(tc_gemm,   cudaFuncAttributeMaxDynamicSharedMemorySize, DSM);
  cudaFuncSetAttribute(fused_rnn, cudaFuncAttributeMaxDynamicSharedMemorySize, FSM);

  cudaMemcpyAsync(xcur, x, SZ * sizeof(float), cudaMemcpyDeviceToDevice);
  cudaMemcpyAsync(Tf + 1 * S, L_row, SZ * sizeof(float), cudaMemcpyDeviceToDevice);
  cudaMemcpyAsync(Tf + 6 * S, L_col, SZ * sizeof(float), cudaMemcpyDeviceToDevice);
  {
    dim3 g(SZ / 1024, 1, 2);
    split_kernel<<<g, 256>>>(Tf + S, Tsh + S, Tsl + S, 5 * S, 5 * S);
  }
  {  // x split -> Ys slot 0 (bf-GEMM A operand for i=0)
    dim3 g(SZ / 1024, 1, 1);
    split_kernel<<<g, 256>>>(xcur, Ysh, Ysl, 0, 0);
  }

  // Chebyshev: T_k = 2*L@T_{k-1} - T_{k-2}; epilogue emits fp32 + split
  for (int k = 2; k <= 4; k++) {
    dim3 g(6, 12, 2);
    int cinmode = (k == 2) ? 1 : 2;
    const float* cin = (k == 2) ? (const float*)0 : (Tf + (ll)(k - 2) * S);
    tc_gemm<<<g, 256, DSM>>>(
        Tsh + S, Tsl + S,
        Tsh + (ll)(k - 1) * S, Tsl + (ll)(k - 1) * S,
        cin, Tf + (ll)k * S, Tsh + (ll)k * S, Tsl + (ll)k * S,
        5 * S, 0, 1,
        5 * S, 0, 1,
        5 * S, 5 * S, 2.0f, -1.0f, cinmode);
  }

  SrcPtrs sp;
  for (int i = 0; i < 5; i++)
    for (int j = 0; j < 5; j++)
      sp.p[i * 5 + j] = (j == 0)
          ? ((i == 0) ? (const float*)xcur : (Yf + (ll)(i - 1) * S))
          : (bff + (ll)(i * 4 + j - 1) * S);

  for (int it = 0; it < 3; it++) {
    {
      dim3 g(24, 24);
      dim3 b(32, 8);
      tsplit_kernel<<<g, b>>>(xcur, xTh, xTl);
    }
    // Y_{1+z} = Tr_{1+z} @ x (B~ = x^T); epilogue emits Yf + Ys split slots 1..4
    {
      dim3 g(6, 12, 4);
      tc_gemm<<<g, 256, DSM>>>(
          Tsh + S, Tsl + S, xTh, xTl,
          (const float*)0, Yf, Ysh + S, Ysl + S,
          S, 0, 1,    0, 0, 1,
          0, S, 1.0f, 0.0f, 0);
    }
    // bf[z] = Y_{z/4} @ Tc_{1+z%4}  (Ys slot 0 = x split), z = 0..19
    {
      dim3 g(6, 12, 20);
      tc_gemm<<<g, 256, DSM>>>(
          Ysh, Ysl, Tsh + 6 * S, Tsl + 6 * S,
          (const float*)0, bff, (__nv_bfloat16*)0, (__nv_bfloat16*)0,
          0, S, 4,    0, S, 4,
          0, S, 1.0f, 0.0f, 0);
    }
    fused_rnn<<<SZ / 128, 256, FSM>>>(
        sp, theta, bias,
        W_f, U_f, b_f, W_i, U_i, b_i, W_o, U_o, b_o, W_c, U_c, b_c,
        W_out, b_out, c, hh, hl, xcur, Ysh, Ysl,
        (it == 0) ? 1 : 0, (it == 2) ? 1 : 0);
  }
}

// round 7
// speedup vs baseline: 1.0211x; 1.0211x over previous
#include <cuda_runtime.h>
#include <cuda_bf16.h>
#include <cstdint>

#define ND 768
#define SZ (768*768)
#define MNTOT SZ
typedef long long ll;

// ---------------- scratch (device globals) ----------------------------------
__device__ float g_Tf[10*SZ];                         // fp32 T[side][k]
__device__ __align__(16) __nv_bfloat16 g_Tsh[10*SZ];  // split hi
__device__ __align__(16) __nv_bfloat16 g_Tsl[10*SZ];  // split lo
__device__ __align__(16) __nv_bfloat16 g_xTh[SZ];
__device__ __align__(16) __nv_bfloat16 g_xTl[SZ];
__device__ float g_Yf[4*SZ];                          // Y_1..Y_4 fp32
__device__ __align__(16) __nv_bfloat16 g_Ysh[5*SZ];   // slot0 = x split
__device__ __align__(16) __nv_bfloat16 g_Ysl[5*SZ];
__device__ float g_bff[20*SZ];
__device__ float g_h[32*SZ];
__device__ float g_c[32*SZ];

struct SrcPtrs { const float* p[25]; };

// ---------------- helpers -----------------------------------------------------
// SW64: conflict-free for 64-byte rows (atom = 8 rows x 64B)
#define SWZ64(x) ((x) ^ (((x) >> 3) & 0x30))

__device__ __forceinline__ uint32_t smem_u32(const void* p) {
  uint32_t a;
  asm("{ .reg .u64 t; cvta.to.shared.u64 t, %1; cvt.u32.u64 %0, t; }"
      : "=r"(a) : "l"(p));
  return a;
}

__device__ __forceinline__ void cpa16(uint32_t dst, const void* src) {
  asm volatile("cp.async.cg.shared.global [%0], [%1], 16;"
               :: "r"(dst), "l"(src) : "memory");
}
#define CP_COMMIT() asm volatile("cp.async.commit_group;" ::: "memory")
#define CP_WAIT(n)  asm volatile("cp.async.wait_group %0;" :: "n"(n) : "memory")

__device__ __forceinline__ void ldm4(uint32_t* r, uint32_t addr) {
  asm volatile("ldmatrix.sync.aligned.m8n8.x4.shared.b16 {%0,%1,%2,%3}, [%4];"
               : "=r"(r[0]), "=r"(r[1]), "=r"(r[2]), "=r"(r[3]) : "r"(addr));
}

__device__ __forceinline__ void mma16816(float* c, const uint32_t* a,
                                         const uint32_t* b) {
  asm volatile(
      "mma.sync.aligned.m16n8k16.row.col.f32.bf16.bf16.f32 "
      "{%0,%1,%2,%3},{%4,%5,%6,%7},{%8,%9},{%0,%1,%2,%3};"
      : "+f"(c[0]), "+f"(c[1]), "+f"(c[2]), "+f"(c[3])
      : "r"(a[0]), "r"(a[1]), "r"(a[2]), "r"(a[3]), "r"(b[0]), "r"(b[1]));
}

__device__ __forceinline__ uint32_t pack2(__nv_bfloat16 a, __nv_bfloat16 b) {
  __nv_bfloat162 t(a, b);
  return *reinterpret_cast<uint32_t*>(&t);
}

// load one 32-wide K chunk of 4 matrices (Ah[TM],Al[TM],Bh[128],Bl[128])
template<int TM>
__device__ __forceinline__ void load_chunk(
    uint32_t sb, int s, int kc, int tid, int brow, int bcol,
    const __nv_bfloat16* a0, const __nv_bfloat16* a1,
    const __nv_bfloat16* b0, const __nv_bfloat16* b1)
{
  constexpr int ASTAGE = TM * 64;              // bytes per A matrix per stage
  constexpr int BSTAGE = 128 * 64;             // 8 KB
  constexpr int STAGE  = 2 * ASTAGE + 2 * BSTAGE;
  constexpr int ITER   = (2 * TM + 256) * 4 / 256;
#pragma unroll
  for (int i = 0; i < ITER; i++) {
    int idx = tid + i * 256;
    int c2 = idx & 3;
    int rowIdx = idx >> 2;
    const __nv_bfloat16* src;
    uint32_t dstbase;
    if (rowIdx < 2 * TM) {                 // uniform per i after unroll
      int mat = rowIdx / TM;
      int row = rowIdx % TM;
      src = (mat ? a1 : a0) + (ll)(brow + row) * ND + kc * 32 + c2 * 8;
      dstbase = mat * ASTAGE + SWZ64(row * 64 + c2 * 16);
    } else {
      int rr = rowIdx - 2 * TM;
      int mat = rr >> 7;
      int row = rr & 127;
      src = (mat ? b1 : b0) + (ll)(bcol + row) * ND + kc * 32 + c2 * 8;
      dstbase = 2 * ASTAGE + mat * BSTAGE + SWZ64(row * 64 + c2 * 16);
    }
    cpa16(sb + s * STAGE + dstbase, src);
  }
}

// ---------------- tensor-core GEMM: C = alpha*A@B~^T + beta*Cin --------------
// TMx128 tile, KC=32, 3-stage cp.async, 2 CTAs/SM.
// A,B fp32-as-split-bf16 (hi+lo). B~ is [N,K] K-major (symmetric ops pass B).
// offA = sAz*z + sAdiv*(z/adiv); offB = sBz*z + sBmod*(z%bmod)
// cinmode: 0 none, 1 identity (+beta on diag), 2 pointer.
// Couth/Coutl non-null -> also emit split-bf16 copy of C.
template<int TM>
__global__ __launch_bounds__(256, 2) void tc_gemm(
    const __nv_bfloat16* __restrict__ Ah, const __nv_bfloat16* __restrict__ Al,
    const __nv_bfloat16* __restrict__ Bh, const __nv_bfloat16* __restrict__ Bl,
    const float* __restrict__ Cin, float* __restrict__ Cout,
    __nv_bfloat16* __restrict__ Couth, __nv_bfloat16* __restrict__ Coutl,
    ll sAz, ll sAdiv, int adiv,
    ll sBz, ll sBmod, int bmod,
    ll sCinz, ll sCz, float alpha, float beta, int cinmode)
{
  extern __shared__ char dsm[];
  constexpr int ASTAGE = TM * 64;
  constexpr int BSTAGE = 128 * 64;
  constexpr int STAGE  = 2 * ASTAGE + 2 * BSTAGE;
  constexpr int NI = (TM == 128) ? 8 : 4;      // n8 frags per warp
  constexpr int NPAIR = NI / 4;                // nj pairs (2 n16 per pair)

  int z = blockIdx.z;
  ll offA = sAz * z + sAdiv * (z / adiv);
  ll offB = sBz * z + sBmod * (z % bmod);
  const __nv_bfloat16* ah = Ah + offA;
  const __nv_bfloat16* al = Al + offA;
  const __nv_bfloat16* bh = Bh + offB;
  const __nv_bfloat16* bl = Bl + offB;
  const int brow = blockIdx.y * TM;
  const int bcol = blockIdx.x * 128;

  int tid = threadIdx.x;
  int lane = tid & 31;
  int wid = tid >> 5;
  int wrow, wcol;
  if (TM == 128) { wrow = (wid & 3) * 32; wcol = (wid >> 2) * 64; }
  else           { wrow = (wid & 1) * 32; wcol = (wid >> 1) * 32; }

  uint32_t raw = smem_u32(dsm);
  uint32_t sb = (raw + 1023) & ~1023u;

  float acc[2][NI][4];
#pragma unroll
  for (int mi = 0; mi < 2; mi++)
#pragma unroll
    for (int ni = 0; ni < NI; ni++)
#pragma unroll
      for (int e = 0; e < 4; e++) acc[mi][ni][e] = 0.0f;

  int a_r  = (lane & 7) + ((lane >> 3) & 1) * 8;
  int a_k8 = ((lane >> 4) & 1) * 8;
  int b_r  = (lane & 7) + ((lane >> 4) & 1) * 8;
  int b_k8 = ((lane >> 3) & 1) * 8;

  load_chunk<TM>(sb, 0, 0, tid, brow, bcol, ah, al, bh, bl); CP_COMMIT();
  load_chunk<TM>(sb, 1, 1, tid, brow, bcol, ah, al, bh, bl); CP_COMMIT();

  for (int kc = 0; kc < 24; kc++) {
    if (kc < 23) { CP_WAIT(1); } else { CP_WAIT(0); }
    __syncthreads();

    uint32_t st  = sb + (kc % 3) * STAGE;
    uint32_t tAh = st;
    uint32_t tAl = st + ASTAGE;
    uint32_t tBh = st + 2 * ASTAGE;
    uint32_t tBl = tBh + BSTAGE;

#pragma unroll
    for (int s = 0; s < 2; s++) {
      uint32_t fah[2][4], fal[2][4];
#pragma unroll
      for (int mi = 0; mi < 2; mi++) {
        int r = wrow + mi * 16 + a_r;
        uint32_t off = SWZ64(r * 64 + (s * 16 + a_k8) * 2);
        ldm4(fah[mi], tAh + off);
        ldm4(fal[mi], tAl + off);
      }
#pragma unroll
      for (int p = 0; p < NPAIR; p++) {
        uint32_t fbh[4][2], fbl[4][2];
#pragma unroll
        for (int nj2 = 0; nj2 < 2; nj2++) {
          int r = wcol + (p * 2 + nj2) * 16 + b_r;
          uint32_t off = SWZ64(r * 64 + (s * 16 + b_k8) * 2);
          uint32_t t4[4];
          ldm4(t4, tBh + off);
          fbh[nj2 * 2][0] = t4[0]; fbh[nj2 * 2][1] = t4[1];
          fbh[nj2 * 2 + 1][0] = t4[2]; fbh[nj2 * 2 + 1][1] = t4[3];
          ldm4(t4, tBl + off);
          fbl[nj2 * 2][0] = t4[0]; fbl[nj2 * 2][1] = t4[1];
          fbl[nj2 * 2 + 1][0] = t4[2]; fbl[nj2 * 2 + 1][1] = t4[3];
        }
#pragma unroll
        for (int mi = 0; mi < 2; mi++)
#pragma unroll
          for (int nl = 0; nl < 4; nl++)
            mma16816(acc[mi][p * 4 + nl], fah[mi], fbh[nl]);
#pragma unroll
        for (int mi = 0; mi < 2; mi++)
#pragma unroll
          for (int nl = 0; nl < 4; nl++)
            mma16816(acc[mi][p * 4 + nl], fah[mi], fbl[nl]);
#pragma unroll
        for (int mi = 0; mi < 2; mi++)
#pragma unroll
          for (int nl = 0; nl < 4; nl++)
            mma16816(acc[mi][p * 4 + nl], fal[mi], fbh[nl]);
      }
    }

    if (kc + 2 < 24) {
      load_chunk<TM>(sb, (kc + 2) % 3, kc + 2, tid, brow, bcol, ah, al, bh, bl);
      CP_COMMIT();
    }
  }

  // ---- epilogue: registers -> gmem (fp32 + optional split bf16) -------------
  const float* cinp = (cinmode == 2) ? (Cin + sCinz * z) : (const float*)0;
  float* co = Cout + sCz * z;
  __nv_bfloat16* coh = Couth ? (Couth + sCz * z) : (__nv_bfloat16*)0;
  __nv_bfloat16* col = Coutl ? (Coutl + sCz * z) : (__nv_bfloat16*)0;
  int qr = lane >> 2, qc = lane & 3;

#pragma unroll
  for (int mi = 0; mi < 2; mi++) {
#pragma unroll
    for (int ni = 0; ni < NI; ni++) {
      int gr0 = brow + wrow + mi * 16 + qr;
      int gc  = bcol + wcol + ni * 8 + qc * 2;
      float2 v0, v1;
      v0.x = alpha * acc[mi][ni][0];
      v0.y = alpha * acc[mi][ni][1];
      v1.x = alpha * acc[mi][ni][2];
      v1.y = alpha * acc[mi][ni][3];
      if (cinmode == 2) {
        float2 c0 = *(const float2*)&cinp[(ll)gr0 * ND + gc];
        float2 c1 = *(const float2*)&cinp[(ll)(gr0 + 8) * ND + gc];
        v0.x += beta * c0.x; v0.y += beta * c0.y;
        v1.x += beta * c1.x; v1.y += beta * c1.y;
      } else if (cinmode == 1) {
        if (gr0 == gc)         v0.x += beta;
        if (gr0 == gc + 1)     v0.y += beta;
        if (gr0 + 8 == gc)     v1.x += beta;
        if (gr0 + 8 == gc + 1) v1.y += beta;
      }
      *(float2*)&co[(ll)gr0 * ND + gc]       = v0;
      *(float2*)&co[(ll)(gr0 + 8) * ND + gc] = v1;
      if (coh) {
        __nv_bfloat16 h0 = __float2bfloat16(v0.x);
        __nv_bfloat16 h1 = __float2bfloat16(v0.y);
        __nv_bfloat16 h2 = __float2bfloat16(v1.x);
        __nv_bfloat16 h3 = __float2bfloat16(v1.y);
        *(uint32_t*)&coh[(ll)gr0 * ND + gc]       = pack2(h0, h1);
        *(uint32_t*)&coh[(ll)(gr0 + 8) * ND + gc] = pack2(h2, h3);
        *(uint32_t*)&col[(ll)gr0 * ND + gc] =
            pack2(__float2bfloat16(v0.x - __bfloat162float(h0)),
                  __float2bfloat16(v0.y - __bfloat162float(h1)));
        *(uint32_t*)&col[(ll)(gr0 + 8) * ND + gc] =
            pack2(__float2bfloat16(v1.x - __bfloat162float(h2)),
                  __float2bfloat16(v1.y - __bfloat162float(h3)));
      }
    }
  }
}

// ---------------- fp32 -> split bf16 (setup only) ----------------------------
__global__ __launch_bounds__(256) void split_kernel(
    const float* __restrict__ src, __nv_bfloat16* __restrict__ hi,
    __nv_bfloat16* __restrict__ lo, ll sS, ll sD)
{
  ll so = sS * blockIdx.z, dofs = sD * blockIdx.z;
  int idx = blockIdx.x * 256 + threadIdx.x;
  float4 v = *(const float4*)(src + so + (ll)idx * 4);
  float a[4] = {v.x, v.y, v.z, v.w};
  __nv_bfloat16 h[4], l[4];
#pragma unroll
  for (int e = 0; e < 4; e++) {
    h[e] = __float2bfloat16(a[e]);
    l[e] = __float2bfloat16(a[e] - __bfloat162float(h[e]));
  }
  uint2 uh, ul;
  uh.x = pack2(h[0], h[1]); uh.y = pack2(h[2], h[3]);
  ul.x = pack2(l[0], l[1]); ul.y = pack2(l[2], l[3]);
  *(uint2*)(hi + dofs + (ll)idx * 4) = uh;
  *(uint2*)(lo + dofs + (ll)idx * 4) = ul;
}

// ---------------- transpose + split: xT = x^T --------------------------------
__global__ void tsplit_kernel(const float* __restrict__ src,
                              __nv_bfloat16* __restrict__ th,
                              __nv_bfloat16* __restrict__ tl)
{
  __shared__ float t[32][33];
  int bx = blockIdx.x * 32, by = blockIdx.y * 32;
  int tx = threadIdx.x, ty = threadIdx.y;
#pragma unroll
  for (int i = 0; i < 4; i++)
    t[ty + 8 * i][tx] = src[(ll)(by + ty + 8 * i) * ND + bx + tx];
  __syncthreads();
#pragma unroll
  for (int i = 0; i < 4; i++) {
    float a = t[tx][ty + 8 * i];
    __nv_bfloat16 h = __float2bfloat16(a);
    __nv_bfloat16 l = __float2bfloat16(a - __bfloat162float(h));
    ll o = (ll)(bx + ty + 8 * i) * ND + by + tx;
    th[o] = h;
    tl[o] = l;
  }
}

// ---------------- fused conv-combine + LSTM gates + dx + x-split -------------
// (round-4/5 version: FFMA gates, fp32 h/c — measured best)
__device__ __forceinline__ float sigf(float v) {
  return __fdividef(1.0f, 1.0f + __expf(-v));
}

__global__ __launch_bounds__(256) void fused_rnn(
    SrcPtrs srcs, const float* __restrict__ theta, const float* __restrict__ bias,
    const float* __restrict__ Wf, const float* __restrict__ Uf, const float* __restrict__ bf_,
    const float* __restrict__ Wi, const float* __restrict__ Ui, const float* __restrict__ bi_,
    const float* __restrict__ Wo, const float* __restrict__ Uo, const float* __restrict__ bo_,
    const float* __restrict__ Wc, const float* __restrict__ Uc, const float* __restrict__ bc_,
    const float* __restrict__ Wout, const float* __restrict__ bout,
    float* h, float* c, float* x,
    __nv_bfloat16* __restrict__ xsh, __nv_bfloat16* __restrict__ xsl,
    int first, int last)
{
  extern __shared__ float ds[];
  float* th  = ds;           // 800
  float* bs  = ds + 800;     // 32
  float* swo = ds + 832;     // 32
  float* sbg = ds + 864;     // 128
  float* sW  = ds + 992;     // 4096
  float* sU  = ds + 5088;    // 4096
  float* sxc = ds + 9184;    // 4096
  float* sdx = ds + 13280;   // 128*9

  int t = threadIdx.x;
  for (int i = t; i < 800; i += 256) th[i] = theta[i];
  if (t < 32) { bs[t] = bias[t]; swo[t] = Wout[t]; }
  {
    const float* Ws[4] = {Wf, Wi, Wo, Wc};
    const float* Us[4] = {Uf, Ui, Uo, Uc};
    for (int idx = t; idx < 4096; idx += 256) {
      int k = idx >> 7, g = (idx >> 5) & 3, o = idx & 31;
      sW[(k * 4 + g) * 32 + o] = Ws[g][k * 32 + o];
      if (!first) sU[(k * 4 + g) * 32 + o] = Us[g][k * 32 + o];
    }
    if (t < 128) { const float* bx[4] = {bf_, bi_, bo_, bc_}; sbg[t] = bx[t >> 5][t & 31]; }
  }
  __syncthreads();

  // ---- phase 1: conv combine -> sxc[k][r]
  {
    int r  = t & 127;
    int oh = (t >> 7) * 16;
    size_t rg = (size_t)blockIdx.x * 128 + r;
    float out[16];
#pragma unroll
    for (int o = 0; o < 16; o++) out[o] = bs[oh + o];
#pragma unroll
    for (int ij = 0; ij < 25; ij++) {
      float v = __ldg(srcs.p[ij] + rg);
      const float* tw = &th[ij * 32 + oh];
#pragma unroll
      for (int o = 0; o < 16; o++) out[o] += v * tw[o];
    }
#pragma unroll
    for (int o = 0; o < 16; o++) sxc[(oh + o) * 128 + r] = out[o];
  }
  __syncthreads();

  // ---- phase 2: gate GEMM (K=32)
  int rt = t & 31, ot = t >> 5;
  size_t r0 = (size_t)blockIdx.x * 128 + rt * 4;
  int ob = ot * 4;

  float acc[4][4][4];
#pragma unroll
  for (int o = 0; o < 4; o++)
#pragma unroll
    for (int g = 0; g < 4; g++)
#pragma unroll
      for (int rr = 0; rr < 4; rr++) acc[o][g][rr] = 0.0f;

  if (first) {
#pragma unroll 4
    for (int k = 0; k < 32; k++) {
      float4 xv = *(const float4*)&sxc[k * 128 + rt * 4];
      float xr[4] = {xv.x, xv.y, xv.z, xv.w};
#pragma unroll
      for (int g = 0; g < 4; g++) {
        float4 w4 = *(const float4*)&sW[(k * 4 + g) * 32 + ob];
        float w[4] = {w4.x, w4.y, w4.z, w4.w};
#pragma unroll
        for (int o = 0; o < 4; o++)
#pragma unroll
          for (int rr = 0; rr < 4; rr++)
            acc[o][g][rr] += w[o] * xr[rr];
      }
    }
  } else {
#pragma unroll 4
    for (int k = 0; k < 32; k++) {
      float4 xv = *(const float4*)&sxc[k * 128 + rt * 4];
      float4 hv = *(const float4*)&h[(size_t)k * MNTOT + r0];
      float xr[4] = {xv.x, xv.y, xv.z, xv.w};
      float hr[4] = {hv.x, hv.y, hv.z, hv.w};
#pragma unroll
      for (int g = 0; g < 4; g++) {
        float4 w4 = *(const float4*)&sW[(k * 4 + g) * 32 + ob];
        float4 u4 = *(const float4*)&sU[(k * 4 + g) * 32 + ob];
        float w[4] = {w4.x, w4.y, w4.z, w4.w};
        float u[4] = {u4.x, u4.y, u4.z, u4.w};
#pragma unroll
        for (int o = 0; o < 4; o++)
#pragma unroll
          for (int rr = 0; rr < 4; rr++)
            acc[o][g][rr] += w[o] * xr[rr] + u[o] * hr[rr];
      }
    }
  }
  __syncthreads();

  // ---- phase 3: epilogue + dx partials
  float pd[4] = {0.0f, 0.0f, 0.0f, 0.0f};
#pragma unroll
  for (int o = 0; o < 4; o++) {
    int oo = ob + o;
    float co[4] = {0.0f, 0.0f, 0.0f, 0.0f};
    if (!first) {
      float4 c4 = *(const float4*)&c[(size_t)oo * MNTOT + r0];
      co[0] = c4.x; co[1] = c4.y; co[2] = c4.z; co[3] = c4.w;
    }
    float cn[4], hn[4];
#pragma unroll
    for (int rr = 0; rr < 4; rr++) {
      float ig = sigf(acc[o][1][rr] + sbg[32 + oo]);
      float cu = sigf(acc[o][3][rr] + sbg[96 + oo]);
      float cnew = ig * cu;
      if (!first) {
        float fg = sigf(acc[o][0][rr] + sbg[oo]);
        cnew += fg * co[rr];
      }
      cn[rr] = cnew;
      pd[rr] += cnew * swo[oo];
      if (!last) {
        float og = sigf(acc[o][2][rr] + sbg[64 + oo]);
        hn[rr] = og * sigf(cnew);
      }
    }
    if (!last) {
      float4 cv; cv.x = cn[0]; cv.y = cn[1]; cv.z = cn[2]; cv.w = cn[3];
      float4 hv; hv.x = hn[0]; hv.y = hn[1]; hv.z = hn[2]; hv.w = hn[3];
      *(float4*)&c[(size_t)oo * MNTOT + r0] = cv;
      *(float4*)&h[(size_t)oo * MNTOT + r0] = hv;
    }
  }
#pragma unroll
  for (int rr = 0; rr < 4; rr++)
    sdx[(rt * 4 + rr) * 9 + ot] = pd[rr];
  __syncthreads();

  if (t < 128) {
    float s = __ldg(bout);
#pragma unroll
    for (int o2 = 0; o2 < 8; o2++) s += sdx[t * 9 + o2];
    size_t gi = (size_t)blockIdx.x * 128 + t;
    float xn = x[gi] + tanhf(s);
    x[gi] = xn;
    if (!last) {
      __nv_bfloat16 hh = __float2bfloat16(xn);
      xsh[gi] = hh;
      xsl[gi] = __float2bfloat16(xn - __bfloat162float(hh));
    }
  }
}

// ---------------- orchestration ----------------------------------------------
extern "C" void kernel_launch(void* const* d_in, const int* in_sizes, int n_in,
                              void* d_out, int out_size)
{
  const float* x     = (const float*)d_in[0];
  const float* L_row = (const float*)d_in[1];
  const float* L_col = (const float*)d_in[2];
  const float* theta = (const float*)d_in[3];
  const float* bias  = (const float*)d_in[4];
  const float* W_f = (const float*)d_in[5];
  const float* U_f = (const float*)d_in[6];
  const float* b_f = (const float*)d_in[7];
  const float* W_i = (const float*)d_in[8];
  const float* U_i = (const float*)d_in[9];
  const float* b_i = (const float*)d_in[10];
  const float* W_o = (const float*)d_in[11];
  const float* U_o = (const float*)d_in[12];
  const float* b_o = (const float*)d_in[13];
  const float* W_c = (const float*)d_in[14];
  const float* U_c = (const float*)d_in[15];
  const float* b_c = (const float*)d_in[16];
  const float* W_out = (const float*)d_in[17];
  const float* b_out = (const float*)d_in[18];
  // d_in[19] = nb_iterations_rnn = 3 (fixed by setup)

  float* xcur = (float*)d_out;

  float *Tf, *Yf, *bff, *h, *c;
  __nv_bfloat16 *Tsh, *Tsl, *xTh, *xTl, *Ysh, *Ysl;
  cudaGetSymbolAddress((void**)&Tf,  g_Tf);
  cudaGetSymbolAddress((void**)&Tsh, g_Tsh);
  cudaGetSymbolAddress((void**)&Tsl, g_Tsl);
  cudaGetSymbolAddress((void**)&xTh, g_xTh);
  cudaGetSymbolAddress((void**)&xTl, g_xTl);
  cudaGetSymbolAddress((void**)&Yf,  g_Yf);
  cudaGetSymbolAddress((void**)&Ysh, g_Ysh);
  cudaGetSymbolAddress((void**)&Ysl, g_Ysl);
  cudaGetSymbolAddress((void**)&bff, g_bff);
  cudaGetSymbolAddress((void**)&h,   g_h);
  cudaGetSymbolAddress((void**)&c,   g_c);

  const ll S = SZ;
  const int DSM128 = 1024 + 3 * 32768;   // 3-stage, TM=128, KC=32 -> 2 CTAs/SM
  const int DSM64  = 1024 + 3 * 24576;   // 3-stage, TM=64
  const int FSM    = (800 + 32 + 32 + 128 + 4096 * 3 + 128 * 9) * 4;
  cudaFuncSetAttribute(tc_gemm<128>, cudaFuncAttributeMaxDynamicSharedMemorySize, DSM128);
  cudaFuncSetAttribute(tc_gemm<64>,  cudaFuncAttributeMaxDynamicSharedMemorySize, DSM64);
  cudaFuncSetAttribute(fused_rnn,    cudaFuncAttributeMaxDynamicSharedMemorySize, FSM);

  cudaMemcpyAsync(xcur, x, SZ * sizeof(float), cudaMemcpyDeviceToDevice);
  cudaMemcpyAsync(Tf + 1 * S, L_row, SZ * sizeof(float), cudaMemcpyDeviceToDevice);
  cudaMemcpyAsync(Tf + 6 * S, L_col, SZ * sizeof(float), cudaMemcpyDeviceToDevice);
  {
    dim3 g(SZ / 1024, 1, 2);
    split_kernel<<<g, 256>>>(Tf + S, Tsh + S, Tsl + S, 5 * S, 5 * S);
  }
  {  // x split -> Ys slot 0 (bf-GEMM A operand for i=0)
    dim3 g(SZ / 1024, 1, 1);
    split_kernel<<<g, 256>>>(xcur, Ysh, Ysl, 0, 0);
  }

  // Chebyshev: T_k = 2*L@T_{k-1} - T_{k-2}; epilogue emits fp32 + split
  for (int k = 2; k <= 4; k++) {
    dim3 g(6, 12, 2);
    int cinmode = (k == 2) ? 1 : 2;
    const float* cin = (k == 2) ? (const float*)0 : (Tf + (ll)(k - 2) * S);
    tc_gemm<64><<<g, 256, DSM64>>>(
        Tsh + S, Tsl + S,
        Tsh + (ll)(k - 1) * S, Tsl + (ll)(k - 1) * S,
        cin, Tf + (ll)k * S, Tsh + (ll)k * S, Tsl + (ll)k * S,
        5 * S, 0, 1,
        5 * S, 0, 1,
        5 * S, 5 * S, 2.0f, -1.0f, cinmode);
  }

  SrcPtrs sp;
  for (int i = 0; i < 5; i++)
    for (int j = 0; j < 5; j++)
      sp.p[i * 5 + j] = (j == 0)
          ? ((i == 0) ? (const float*)xcur : (Yf + (ll)(i - 1) * S))
          : (bff + (ll)(i * 4 + j - 1) * S);

  for (int it = 0; it < 3; it++) {
    {
      dim3 g(24, 24);
      dim3 b(32, 8);
      tsplit_kernel<<<g, b>>>(xcur, xTh, xTl);
    }
    // Y_{1+z} = Tr_{1+z} @ x (B~ = x^T); emits Yf + Ys split slots 1..4
    {
      dim3 g(6, 12, 4);
      tc_gemm<64><<<g, 256, DSM64>>>(
          Tsh + S, Tsl + S, xTh, xTl,
          (const float*)0, Yf, Ysh + S, Ysl + S,
          S, 0, 1,    0, 0, 1,
          0, S, 1.0f, 0.0f, 0);
    }
    // bf[z] = Y_{z/4} @ Tc_{1+z%4}  (Ys slot 0 = x split), z = 0..19
    {
      dim3 g(6, 6, 20);
      tc_gemm<128><<<g, 256, DSM128>>>(
          Ysh, Ysl, Tsh + 6 * S, Tsl + 6 * S,
          (const float*)0, bff, (__nv_bfloat16*)0, (__nv_bfloat16*)0,
          0, S, 4,    0, S, 4,
          0, S, 1.0f, 0.0f, 0);
    }
    fused_rnn<<<SZ / 128, 256, FSM>>>(
        sp, theta, bias,
        W_f, U_f, b_f, W_i, U_i, b_i, W_o, U_o, b_o, W_c, U_c, b_c,
        W_out, b_out, h, c, xcur, Ysh, Ysl,
        (it == 0) ? 1 : 0, (it == 2) ? 1 : 0);
  }
}

// round 8
// speedup vs baseline: 1.7525x; 1.7164x over previous
#include <cuda_runtime.h>
#include <cuda_bf16.h>
#include <cstdint>

#define ND 768
#define SZ (768*768)
#define MNTOT SZ
typedef long long ll;

// ---------------- scratch (device globals) ----------------------------------
__device__ float g_Tf[10*SZ];                         // fp32 T[side][k]
__device__ __align__(16) __nv_bfloat16 g_Tsh[10*SZ];  // split hi
__device__ __align__(16) __nv_bfloat16 g_Tsl[10*SZ];  // split lo
__device__ __align__(16) __nv_bfloat16 g_xTh[SZ];
__device__ __align__(16) __nv_bfloat16 g_xTl[SZ];
__device__ float g_Yf[4*SZ];                          // Y_1..Y_4 fp32
__device__ __align__(16) __nv_bfloat16 g_Ysh[5*SZ];   // slot0 = x split
__device__ __align__(16) __nv_bfloat16 g_Ysl[5*SZ];
__device__ float g_bff[20*SZ];
__device__ __align__(16) __nv_bfloat16 g_hh[32*SZ];   // h point-major [pt][32] hi
__device__ __align__(16) __nv_bfloat16 g_hl[32*SZ];   // lo
__device__ float g_c[32*SZ];                          // c point-major [pt][32]
__device__ __align__(16) __nv_bfloat16 g_Wth[128*64]; // [n=g*32+o][k] hi (k<32 W, k>=32 U)
__device__ __align__(16) __nv_bfloat16 g_Wtl[128*64]; // lo

struct SrcPtrs { const float* p[25]; };

// ---------------- helpers -----------------------------------------------------
#define SWZ(x)   ((x) ^ (((x) >> 3) & 0x70))   // 128B rows
#define SWZ64(x) ((x) ^ (((x) >> 3) & 0x30))   // 64B rows

__device__ __forceinline__ uint32_t smem_u32(const void* p) {
  uint32_t a;
  asm("{ .reg .u64 t; cvta.to.shared.u64 t, %1; cvt.u32.u64 %0, t; }"
      : "=r"(a) : "l"(p));
  return a;
}

__device__ __forceinline__ void cpa16(uint32_t dst, const void* src) {
  asm volatile("cp.async.cg.shared.global [%0], [%1], 16;"
               :: "r"(dst), "l"(src) : "memory");
}
#define CP_COMMIT() asm volatile("cp.async.commit_group;" ::: "memory")
#define CP_WAIT(n)  asm volatile("cp.async.wait_group %0;" :: "n"(n) : "memory")

__device__ __forceinline__ void ldm4(uint32_t* r, uint32_t addr) {
  asm volatile("ldmatrix.sync.aligned.m8n8.x4.shared.b16 {%0,%1,%2,%3}, [%4];"
               : "=r"(r[0]), "=r"(r[1]), "=r"(r[2]), "=r"(r[3]) : "r"(addr));
}

__device__ __forceinline__ void mma16816(float* c, const uint32_t* a,
                                         const uint32_t* b) {
  asm volatile(
      "mma.sync.aligned.m16n8k16.row.col.f32.bf16.bf16.f32 "
      "{%0,%1,%2,%3},{%4,%5,%6,%7},{%8,%9},{%0,%1,%2,%3};"
      : "+f"(c[0]), "+f"(c[1]), "+f"(c[2]), "+f"(c[3])
      : "r"(a[0]), "r"(a[1]), "r"(a[2]), "r"(a[3]), "r"(b[0]), "r"(b[1]));
}

__device__ __forceinline__ uint32_t pack2(__nv_bfloat16 a, __nv_bfloat16 b) {
  __nv_bfloat162 t(a, b);
  return *reinterpret_cast<uint32_t*>(&t);
}

// load one 32-wide K chunk of 4 matrices (Ah[TM],Al[TM],Bh[128],Bl[128])
template<int TM>
__device__ __forceinline__ void load_chunk(
    uint32_t sb, int s, int kc, int tid, int brow, int bcol,
    const __nv_bfloat16* a0, const __nv_bfloat16* a1,
    const __nv_bfloat16* b0, const __nv_bfloat16* b1)
{
  constexpr int ASTAGE = TM * 64;
  constexpr int BSTAGE = 128 * 64;
  constexpr int STAGE  = 2 * ASTAGE + 2 * BSTAGE;
  constexpr int ITER   = (2 * TM + 256) * 4 / 256;
#pragma unroll
  for (int i = 0; i < ITER; i++) {
    int idx = tid + i * 256;
    int c2 = idx & 3;
    int rowIdx = idx >> 2;
    const __nv_bfloat16* src;
    uint32_t dstbase;
    if (rowIdx < 2 * TM) {
      int mat = rowIdx / TM;
      int row = rowIdx % TM;
      src = (mat ? a1 : a0) + (ll)(brow + row) * ND + kc * 32 + c2 * 8;
      dstbase = mat * ASTAGE + SWZ64(row * 64 + c2 * 16);
    } else {
      int rr = rowIdx - 2 * TM;
      int mat = rr >> 7;
      int row = rr & 127;
      src = (mat ? b1 : b0) + (ll)(bcol + row) * ND + kc * 32 + c2 * 8;
      dstbase = 2 * ASTAGE + mat * BSTAGE + SWZ64(row * 64 + c2 * 16);
    }
    cpa16(sb + s * STAGE + dstbase, src);
  }
}

// ---------------- tensor-core GEMM (round-7 config, unchanged) ---------------
template<int TM>
__global__ __launch_bounds__(256, 2) void tc_gemm(
    const __nv_bfloat16* __restrict__ Ah, const __nv_bfloat16* __restrict__ Al,
    const __nv_bfloat16* __restrict__ Bh, const __nv_bfloat16* __restrict__ Bl,
    const float* __restrict__ Cin, float* __restrict__ Cout,
    __nv_bfloat16* __restrict__ Couth, __nv_bfloat16* __restrict__ Coutl,
    ll sAz, ll sAdiv, int adiv,
    ll sBz, ll sBmod, int bmod,
    ll sCinz, ll sCz, float alpha, float beta, int cinmode)
{
  extern __shared__ char dsm[];
  constexpr int ASTAGE = TM * 64;
  constexpr int BSTAGE = 128 * 64;
  constexpr int STAGE  = 2 * ASTAGE + 2 * BSTAGE;
  constexpr int NI = (TM == 128) ? 8 : 4;
  constexpr int NPAIR = NI / 4;

  int z = blockIdx.z;
  ll offA = sAz * z + sAdiv * (z / adiv);
  ll offB = sBz * z + sBmod * (z % bmod);
  const __nv_bfloat16* ah = Ah + offA;
  const __nv_bfloat16* al = Al + offA;
  const __nv_bfloat16* bh = Bh + offB;
  const __nv_bfloat16* bl = Bl + offB;
  const int brow = blockIdx.y * TM;
  const int bcol = blockIdx.x * 128;

  int tid = threadIdx.x;
  int lane = tid & 31;
  int wid = tid >> 5;
  int wrow, wcol;
  if (TM == 128) { wrow = (wid & 3) * 32; wcol = (wid >> 2) * 64; }
  else           { wrow = (wid & 1) * 32; wcol = (wid >> 1) * 32; }

  uint32_t raw = smem_u32(dsm);
  uint32_t sb = (raw + 1023) & ~1023u;

  float acc[2][NI][4];
#pragma unroll
  for (int mi = 0; mi < 2; mi++)
#pragma unroll
    for (int ni = 0; ni < NI; ni++)
#pragma unroll
      for (int e = 0; e < 4; e++) acc[mi][ni][e] = 0.0f;

  int a_r  = (lane & 7) + ((lane >> 3) & 1) * 8;
  int a_k8 = ((lane >> 4) & 1) * 8;
  int b_r  = (lane & 7) + ((lane >> 4) & 1) * 8;
  int b_k8 = ((lane >> 3) & 1) * 8;

  load_chunk<TM>(sb, 0, 0, tid, brow, bcol, ah, al, bh, bl); CP_COMMIT();
  load_chunk<TM>(sb, 1, 1, tid, brow, bcol, ah, al, bh, bl); CP_COMMIT();

  for (int kc = 0; kc < 24; kc++) {
    if (kc < 23) { CP_WAIT(1); } else { CP_WAIT(0); }
    __syncthreads();

    uint32_t st  = sb + (kc % 3) * STAGE;
    uint32_t tAh = st;
    uint32_t tAl = st + ASTAGE;
    uint32_t tBh = st + 2 * ASTAGE;
    uint32_t tBl = tBh + BSTAGE;

#pragma unroll
    for (int s = 0; s < 2; s++) {
      uint32_t fah[2][4], fal[2][4];
#pragma unroll
      for (int mi = 0; mi < 2; mi++) {
        int r = wrow + mi * 16 + a_r;
        uint32_t off = SWZ64(r * 64 + (s * 16 + a_k8) * 2);
        ldm4(fah[mi], tAh + off);
        ldm4(fal[mi], tAl + off);
      }
#pragma unroll
      for (int p = 0; p < NPAIR; p++) {
        uint32_t fbh[4][2], fbl[4][2];
#pragma unroll
        for (int nj2 = 0; nj2 < 2; nj2++) {
          int r = wcol + (p * 2 + nj2) * 16 + b_r;
          uint32_t off = SWZ64(r * 64 + (s * 16 + b_k8) * 2);
          uint32_t t4[4];
          ldm4(t4, tBh + off);
          fbh[nj2 * 2][0] = t4[0]; fbh[nj2 * 2][1] = t4[1];
          fbh[nj2 * 2 + 1][0] = t4[2]; fbh[nj2 * 2 + 1][1] = t4[3];
          ldm4(t4, tBl + off);
          fbl[nj2 * 2][0] = t4[0]; fbl[nj2 * 2][1] = t4[1];
          fbl[nj2 * 2 + 1][0] = t4[2]; fbl[nj2 * 2 + 1][1] = t4[3];
        }
#pragma unroll
        for (int mi = 0; mi < 2; mi++)
#pragma unroll
          for (int nl = 0; nl < 4; nl++)
            mma16816(acc[mi][p * 4 + nl], fah[mi], fbh[nl]);
#pragma unroll
        for (int mi = 0; mi < 2; mi++)
#pragma unroll
          for (int nl = 0; nl < 4; nl++)
            mma16816(acc[mi][p * 4 + nl], fah[mi], fbl[nl]);
#pragma unroll
        for (int mi = 0; mi < 2; mi++)
#pragma unroll
          for (int nl = 0; nl < 4; nl++)
            mma16816(acc[mi][p * 4 + nl], fal[mi], fbh[nl]);
      }
    }

    if (kc + 2 < 24) {
      load_chunk<TM>(sb, (kc + 2) % 3, kc + 2, tid, brow, bcol, ah, al, bh, bl);
      CP_COMMIT();
    }
  }

  const float* cinp = (cinmode == 2) ? (Cin + sCinz * z) : (const float*)0;
  float* co = Cout + sCz * z;
  __nv_bfloat16* coh = Couth ? (Couth + sCz * z) : (__nv_bfloat16*)0;
  __nv_bfloat16* col = Coutl ? (Coutl + sCz * z) : (__nv_bfloat16*)0;
  int qr = lane >> 2, qc = lane & 3;

#pragma unroll
  for (int mi = 0; mi < 2; mi++) {
#pragma unroll
    for (int ni = 0; ni < NI; ni++) {
      int gr0 = brow + wrow + mi * 16 + qr;
      int gc  = bcol + wcol + ni * 8 + qc * 2;
      float2 v0, v1;
      v0.x = alpha * acc[mi][ni][0];
      v0.y = alpha * acc[mi][ni][1];
      v1.x = alpha * acc[mi][ni][2];
      v1.y = alpha * acc[mi][ni][3];
      if (cinmode == 2) {
        float2 c0 = *(const float2*)&cinp[(ll)gr0 * ND + gc];
        float2 c1 = *(const float2*)&cinp[(ll)(gr0 + 8) * ND + gc];
        v0.x += beta * c0.x; v0.y += beta * c0.y;
        v1.x += beta * c1.x; v1.y += beta * c1.y;
      } else if (cinmode == 1) {
        if (gr0 == gc)         v0.x += beta;
        if (gr0 == gc + 1)     v0.y += beta;
        if (gr0 + 8 == gc)     v1.x += beta;
        if (gr0 + 8 == gc + 1) v1.y += beta;
      }
      *(float2*)&co[(ll)gr0 * ND + gc]       = v0;
      *(float2*)&co[(ll)(gr0 + 8) * ND + gc] = v1;
      if (coh) {
        __nv_bfloat16 h0 = __float2bfloat16(v0.x);
        __nv_bfloat16 h1 = __float2bfloat16(v0.y);
        __nv_bfloat16 h2 = __float2bfloat16(v1.x);
        __nv_bfloat16 h3 = __float2bfloat16(v1.y);
        *(uint32_t*)&coh[(ll)gr0 * ND + gc]       = pack2(h0, h1);
        *(uint32_t*)&coh[(ll)(gr0 + 8) * ND + gc] = pack2(h2, h3);
        *(uint32_t*)&col[(ll)gr0 * ND + gc] =
            pack2(__float2bfloat16(v0.x - __bfloat162float(h0)),
                  __float2bfloat16(v0.y - __bfloat162float(h1)));
        *(uint32_t*)&col[(ll)(gr0 + 8) * ND + gc] =
            pack2(__float2bfloat16(v1.x - __bfloat162float(h2)),
                  __float2bfloat16(v1.y - __bfloat162float(h3)));
      }
    }
  }
}

// ---------------- fp32 -> split bf16 (setup only) ----------------------------
__global__ __launch_bounds__(256) void split_kernel(
    const float* __restrict__ src, __nv_bfloat16* __restrict__ hi,
    __nv_bfloat16* __restrict__ lo, ll sS, ll sD)
{
  ll so = sS * blockIdx.z, dofs = sD * blockIdx.z;
  int idx = blockIdx.x * 256 + threadIdx.x;
  float4 v = *(const float4*)(src + so + (ll)idx * 4);
  float a[4] = {v.x, v.y, v.z, v.w};
  __nv_bfloat16 h[4], l[4];
#pragma unroll
  for (int e = 0; e < 4; e++) {
    h[e] = __float2bfloat16(a[e]);
    l[e] = __float2bfloat16(a[e] - __bfloat162float(h[e]));
  }
  uint2 uh, ul;
  uh.x = pack2(h[0], h[1]); uh.y = pack2(h[2], h[3]);
  ul.x = pack2(l[0], l[1]); ul.y = pack2(l[2], l[3]);
  *(uint2*)(hi + dofs + (ll)idx * 4) = uh;
  *(uint2*)(lo + dofs + (ll)idx * 4) = ul;
}

// ---------------- W/U -> bf16 hi/lo [n=g*32+o][k] (setup, once) --------------
__global__ void wsplit_kernel(
    const float* __restrict__ Wf, const float* __restrict__ Uf,
    const float* __restrict__ Wi, const float* __restrict__ Ui,
    const float* __restrict__ Wo, const float* __restrict__ Uo,
    const float* __restrict__ Wc, const float* __restrict__ Uc,
    __nv_bfloat16* __restrict__ Wth, __nv_bfloat16* __restrict__ Wtl)
{
  const float* Ws[4] = {Wf, Wi, Wo, Wc};
  const float* Us[4] = {Uf, Ui, Uo, Uc};
  int idx = blockIdx.x * 256 + threadIdx.x;   // 0..8191
  int n = idx >> 6, k = idx & 63;
  int g = n >> 5, o = n & 31;
  float v = (k < 32) ? Ws[g][k * 32 + o] : Us[g][(k - 32) * 32 + o];
  __nv_bfloat16 vh = __float2bfloat16(v);
  Wth[idx] = vh;
  Wtl[idx] = __float2bfloat16(v - __bfloat162float(vh));
}

// ---------------- transpose + split: xT = x^T --------------------------------
__global__ void tsplit_kernel(const float* __restrict__ src,
                              __nv_bfloat16* __restrict__ th,
                              __nv_bfloat16* __restrict__ tl)
{
  __shared__ float t[32][33];
  int bx = blockIdx.x * 32, by = blockIdx.y * 32;
  int tx = threadIdx.x, ty = threadIdx.y;
#pragma unroll
  for (int i = 0; i < 4; i++)
    t[ty + 8 * i][tx] = src[(ll)(by + ty + 8 * i) * ND + bx + tx];
  __syncthreads();
#pragma unroll
  for (int i = 0; i < 4; i++) {
    float a = t[tx][ty + 8 * i];
    __nv_bfloat16 h = __float2bfloat16(a);
    __nv_bfloat16 l = __float2bfloat16(a - __bfloat162float(h));
    ll o = (ll)(bx + ty + 8 * i) * ND + by + tx;
    th[o] = h;
    tl[o] = l;
  }
}

// ---------------- fused_rnn v2: combine + HMMA gates (in-register epilogue) --
// smem from 1024-aligned base:
//   AH [0,16K)  : A tile [128 pt][64 k] bf16 hi, SW128 (k 0-31 xc, 32-63 h)
//   AL [16K,32K): lo
//   BH [32K,48K): W tile [128 n][64 k] bf16 hi, SW128 (n = g*32+o)
//   BL [48K,64K): lo
//   scalars at 64K: th 800f, bs 32f, swo 32f, sbg 128f
__device__ __forceinline__ float sigf(float v) {
  return __fdividef(1.0f, 1.0f + __expf(-v));
}

__global__ __launch_bounds__(256, 2) void fused_rnn(
    SrcPtrs srcs, const float* __restrict__ theta, const float* __restrict__ bias,
    const __nv_bfloat16* __restrict__ Wth, const __nv_bfloat16* __restrict__ Wtl,
    const float* __restrict__ bf_, const float* __restrict__ bi_,
    const float* __restrict__ bo_, const float* __restrict__ bc_,
    const float* __restrict__ Wout, const float* __restrict__ bout,
    float* c, __nv_bfloat16* hh_g, __nv_bfloat16* hl_g, float* x,
    __nv_bfloat16* __restrict__ xsh, __nv_bfloat16* __restrict__ xsl,
    int first, int last)
{
  extern __shared__ char dsm[];
  uint32_t raw = smem_u32(dsm);
  uint32_t sb = (raw + 1023) & ~1023u;
  char* base = dsm + (sb - raw);

  float* th  = (float*)(base + 65536);            // 800
  float* bs  = (float*)(base + 65536 + 3200);     // 32
  float* swo = (float*)(base + 65536 + 3328);     // 32
  float* sbg = (float*)(base + 65536 + 3456);     // 128

  int t = threadIdx.x;
  int lane = t & 31;
  int w = t >> 5;
  size_t bpt = (size_t)blockIdx.x * 128;

  // ---- issue cp.async: W tiles + h rows --------------------------------------
#pragma unroll
  for (int i = 0; i < 8; i++) {         // W hi+lo: 2048 chunks
    int idx = t + i * 256;
    int mat = idx >> 10;                // 0 = hi, 1 = lo (uniform per i)
    int rr  = (idx >> 3) & 127;
    int c4  = idx & 7;
    const __nv_bfloat16* src = (mat ? Wtl : Wth) + rr * 64 + c4 * 8;
    cpa16(sb + 32768 + mat * 16384 + SWZ(rr * 128 + c4 * 16), src);
  }
  if (!first) {
#pragma unroll
    for (int i = 0; i < 8; i++) {       // h hi+lo into A cols 32..63
      int idx = t + i * 256;
      int mat = idx >> 10;
      int rr  = (idx >> 2) & 127;
      int c4h = (idx & 3) + 4;
      const __nv_bfloat16* src =
          (mat ? hl_g : hh_g) + (bpt + rr) * 32 + (c4h - 4) * 8;
      cpa16(sb + mat * 16384 + SWZ(rr * 128 + c4h * 16), src);
    }
  } else {
    uint4 z4 = make_uint4(0, 0, 0, 0);
#pragma unroll
    for (int i = 0; i < 8; i++) {
      int idx = t + i * 256;
      int mat = idx >> 10;
      int rr  = (idx >> 2) & 127;
      int c4h = (idx & 3) + 4;
      *(uint4*)(base + mat * 16384 + SWZ(rr * 128 + c4h * 16)) = z4;
    }
  }
  CP_COMMIT();

  // ---- scalars ---------------------------------------------------------------
  for (int i = t; i < 800; i += 256) th[i] = theta[i];
  if (t < 32) { bs[t] = bias[t]; swo[t] = Wout[t]; }
  if (t < 128) { const float* bx[4] = {bf_, bi_, bo_, bc_}; sbg[t] = bx[t >> 5][t & 31]; }
  __syncthreads();

  // ---- combine -> A cols 0..31 (xc split bf16) -------------------------------
  {
    int r  = t & 127;
    int oh = (t >> 7) * 16;
    size_t rg = bpt + r;
    float out[16];
#pragma unroll
    for (int o = 0; o < 16; o++) out[o] = bs[oh + o];
#pragma unroll
    for (int ij = 0; ij < 25; ij++) {
      float v = __ldg(srcs.p[ij] + rg);
      const float* tw = &th[ij * 32 + oh];
#pragma unroll
      for (int o = 0; o < 16; o++) out[o] += v * tw[o];
    }
#pragma unroll
    for (int i = 0; i < 8; i++) {
      float a0 = out[2 * i], a1 = out[2 * i + 1];
      __nv_bfloat16 h0 = __float2bfloat16(a0);
      __nv_bfloat16 h1 = __float2bfloat16(a1);
      uint32_t byte = r * 128 + (oh + 2 * i) * 2;
      *(uint32_t*)(base + SWZ(byte)) = pack2(h0, h1);
      *(uint32_t*)(base + 16384 + SWZ(byte)) =
          pack2(__float2bfloat16(a0 - __bfloat162float(h0)),
                __float2bfloat16(a1 - __bfloat162float(h1)));
    }
  }
  CP_WAIT(0);
  __syncthreads();

  // ---- HMMA: PRE[128 pt x 128 n] = A @ W^T (3-term split) --------------------
  int a_r  = (lane & 7) + ((lane >> 3) & 1) * 8;
  int a_k8 = ((lane >> 4) & 1) * 8;
  int b_r  = (lane & 7) + ((lane >> 4) & 1) * 8;
  int b_k8 = ((lane >> 3) & 1) * 8;

  float acc[16][4];
#pragma unroll
  for (int nt = 0; nt < 16; nt++)
#pragma unroll
    for (int e = 0; e < 4; e++) acc[nt][e] = 0.0f;

#pragma unroll
  for (int ks = 0; ks < 4; ks++) {
    uint32_t abyte = SWZ((w * 16 + a_r) * 128 + (ks * 16 + a_k8) * 2);
    uint32_t ah4[4], al4[4];
    ldm4(ah4, sb + abyte);
    ldm4(al4, sb + 16384 + abyte);
#pragma unroll
    for (int np = 0; np < 8; np++) {
      uint32_t bbyte = SWZ((np * 16 + b_r) * 128 + (ks * 16 + b_k8) * 2);
      uint32_t bh4[4], bl4[4];
      ldm4(bh4, sb + 32768 + bbyte);
      ldm4(bl4, sb + 49152 + bbyte);
      mma16816(acc[2 * np],     ah4, bh4);
      mma16816(acc[2 * np + 1], ah4, bh4 + 2);
      mma16816(acc[2 * np],     ah4, bl4);
      mma16816(acc[2 * np + 1], ah4, bl4 + 2);
      mma16816(acc[2 * np],     al4, bh4);
      mma16816(acc[2 * np + 1], al4, bh4 + 2);
    }
  }

  // ---- in-register gates + c/h update + dx partials --------------------------
  // lane (qr,qc): acc[4g+m][p+2rh] = preact gate g, o = 8m+2qc+p,
  //               point = bpt + w*16 + qr + 8rh
  int qr = lane >> 2, qc = lane & 3;
  size_t p0 = bpt + w * 16 + qr;
  float pd[2] = {0.0f, 0.0f};

#pragma unroll
  for (int m = 0; m < 4; m++) {
#pragma unroll
    for (int rh = 0; rh < 2; rh++) {
      size_t pt = p0 + 8 * rh;
      int ob = 8 * m + 2 * qc;
      float2 cold = make_float2(0.0f, 0.0f);
      if (!first) cold = *(const float2*)&c[pt * 32 + ob];
      float cn[2], hn[2];
#pragma unroll
      for (int p = 0; p < 2; p++) {
        int o = ob + p;
        int e = p + 2 * rh;
        float zi = acc[4 + m][e]  + sbg[32 + o];
        float zc = acc[12 + m][e] + sbg[96 + o];
        float cnew = sigf(zi) * sigf(zc);
        if (!first) {
          float zf = acc[m][e] + sbg[o];
          cnew += sigf(zf) * (p ? cold.y : cold.x);
        }
        cn[p] = cnew;
        pd[rh] += cnew * swo[o];
        if (!last) {
          float zo = acc[8 + m][e] + sbg[64 + o];
          hn[p] = sigf(zo) * sigf(cnew);
        }
      }
      if (!last) {
        *(float2*)&c[pt * 32 + ob] = make_float2(cn[0], cn[1]);
        __nv_bfloat16 h0 = __float2bfloat16(hn[0]);
        __nv_bfloat16 h1 = __float2bfloat16(hn[1]);
        *(uint32_t*)&hh_g[pt * 32 + ob] = pack2(h0, h1);
        *(uint32_t*)&hl_g[pt * 32 + ob] =
            pack2(__float2bfloat16(hn[0] - __bfloat162float(h0)),
                  __float2bfloat16(hn[1] - __bfloat162float(h1)));
      }
    }
  }

  // reduce dx over the 4 qc-lanes (same points)
#pragma unroll
  for (int rh = 0; rh < 2; rh++) {
    pd[rh] += __shfl_xor_sync(0xFFFFFFFF, pd[rh], 1);
    pd[rh] += __shfl_xor_sync(0xFFFFFFFF, pd[rh], 2);
  }
  if (qc == 0) {
    float b0 = __ldg(bout);
#pragma unroll
    for (int rh = 0; rh < 2; rh++) {
      size_t gi = p0 + 8 * rh;
      float xn = x[gi] + tanhf(pd[rh] + b0);
      x[gi] = xn;
      if (!last) {
        __nv_bfloat16 xh2 = __float2bfloat16(xn);
        xsh[gi] = xh2;
        xsl[gi] = __float2bfloat16(xn - __bfloat162float(xh2));
      }
    }
  }
}

// ---------------- orchestration ----------------------------------------------
extern "C" void kernel_launch(void* const* d_in, const int* in_sizes, int n_in,
                              void* d_out, int out_size)
{
  const float* x     = (const float*)d_in[0];
  const float* L_row = (const float*)d_in[1];
  const float* L_col = (const float*)d_in[2];
  const float* theta = (const float*)d_in[3];
  const float* bias  = (const float*)d_in[4];
  const float* W_f = (const float*)d_in[5];
  const float* U_f = (const float*)d_in[6];
  const float* b_f = (const float*)d_in[7];
  const float* W_i = (const float*)d_in[8];
  const float* U_i = (const float*)d_in[9];
  const float* b_i = (const float*)d_in[10];
  const float* W_o = (const float*)d_in[11];
  const float* U_o = (const float*)d_in[12];
  const float* b_o = (const float*)d_in[13];
  const float* W_c = (const float*)d_in[14];
  const float* U_c = (const float*)d_in[15];
  const float* b_c = (const float*)d_in[16];
  const float* W_out = (const float*)d_in[17];
  const float* b_out = (const float*)d_in[18];
  // d_in[19] = nb_iterations_rnn = 3 (fixed by setup)

  float* xcur = (float*)d_out;

  float *Tf, *Yf, *bff, *c;
  __nv_bfloat16 *Tsh, *Tsl, *xTh, *xTl, *Ysh, *Ysl, *hh, *hl, *Wth, *Wtl;
  cudaGetSymbolAddress((void**)&Tf,  g_Tf);
  cudaGetSymbolAddress((void**)&Tsh, g_Tsh);
  cudaGetSymbolAddress((void**)&Tsl, g_Tsl);
  cudaGetSymbolAddress((void**)&xTh, g_xTh);
  cudaGetSymbolAddress((void**)&xTl, g_xTl);
  cudaGetSymbolAddress((void**)&Yf,  g_Yf);
  cudaGetSymbolAddress((void**)&Ysh, g_Ysh);
  cudaGetSymbolAddress((void**)&Ysl, g_Ysl);
  cudaGetSymbolAddress((void**)&bff, g_bff);
  cudaGetSymbolAddress((void**)&hh,  g_hh);
  cudaGetSymbolAddress((void**)&hl,  g_hl);
  cudaGetSymbolAddress((void**)&c,   g_c);
  cudaGetSymbolAddress((void**)&Wth, g_Wth);
  cudaGetSymbolAddress((void**)&Wtl, g_Wtl);

  const ll S = SZ;
  const int DSM128 = 1024 + 3 * 32768;
  const int DSM64  = 1024 + 3 * 24576;
  const int FSM    = 1024 + 65536 + 3968;
  cudaFuncSetAttribute(tc_gemm<128>, cudaFuncAttributeMaxDynamicSharedMemorySize, DSM128);
  cudaFuncSetAttribute(tc_gemm<64>,  cudaFuncAttributeMaxDynamicSharedMemorySize, DSM64);
  cudaFuncSetAttribute(fused_rnn,    cudaFuncAttributeMaxDynamicSharedMemorySize, FSM);

  cudaMemcpyAsync(xcur, x, SZ * sizeof(float), cudaMemcpyDeviceToDevice);
  cudaMemcpyAsync(Tf + 1 * S, L_row, SZ * sizeof(float), cudaMemcpyDeviceToDevice);
  cudaMemcpyAsync(Tf + 6 * S, L_col, SZ * sizeof(float), cudaMemcpyDeviceToDevice);
  wsplit_kernel<<<32, 256>>>(W_f, U_f, W_i, U_i, W_o, U_o, W_c, U_c, Wth, Wtl);
  {
    dim3 g(SZ / 1024, 1, 2);
    split_kernel<<<g, 256>>>(Tf + S, Tsh + S, Tsl + S, 5 * S, 5 * S);
  }
  {  // x split -> Ys slot 0
    dim3 g(SZ / 1024, 1, 1);
    split_kernel<<<g, 256>>>(xcur, Ysh, Ysl, 0, 0);
  }

  // Chebyshev: T_k = 2*L@T_{k-1} - T_{k-2}; epilogue emits fp32 + split
  for (int k = 2; k <= 4; k++) {
    dim3 g(6, 12, 2);
    int cinmode = (k == 2) ? 1 : 2;
    const float* cin = (k == 2) ? (const float*)0 : (Tf + (ll)(k - 2) * S);
    tc_gemm<64><<<g, 256, DSM64>>>(
        Tsh + S, Tsl + S,
        Tsh + (ll)(k - 1) * S, Tsl + (ll)(k - 1) * S,
        cin, Tf + (ll)k * S, Tsh + (ll)k * S, Tsl + (ll)k * S,
        5 * S, 0, 1,
        5 * S, 0, 1,
        5 * S, 5 * S, 2.0f, -1.0f, cinmode);
  }

  SrcPtrs sp;
  for (int i = 0; i < 5; i++)
    for (int j = 0; j < 5; j++)
      sp.p[i * 5 + j] = (j == 0)
          ? ((i == 0) ? (const float*)xcur : (Yf + (ll)(i - 1) * S))
          : (bff + (ll)(i * 4 + j - 1) * S);

  for (int it = 0; it < 3; it++) {
    {
      dim3 g(24, 24);
      dim3 b(32, 8);
      tsplit_kernel<<<g, b>>>(xcur, xTh, xTl);
    }
    // Y_{1+z} = Tr_{1+z} @ x
    {
      dim3 g(6, 12, 4);
      tc_gemm<64><<<g, 256, DSM64>>>(
          Tsh + S, Tsl + S, xTh, xTl,
          (const float*)0, Yf, Ysh + S, Ysl + S,
          S, 0, 1,    0, 0, 1,
          0, S, 1.0f, 0.0f, 0);
    }
    // bf[z] = Y_{z/4} @ Tc_{1+z%4}
    {
      dim3 g(6, 6, 20);
      tc_gemm<128><<<g, 256, DSM128>>>(
          Ysh, Ysl, Tsh + 6 * S, Tsl + 6 * S,
          (const float*)0, bff, (__nv_bfloat16*)0, (__nv_bfloat16*)0,
          0, S, 4,    0, S, 4,
          0, S, 1.0f, 0.0f, 0);
    }
    fused_rnn<<<SZ / 128, 256, FSM>>>(
        sp, theta, bias, Wth, Wtl,
        b_f, b_i, b_o, b_c, W_out, b_out,
        c, hh, hl, xcur, Ysh, Ysl,
        (it == 0) ? 1 : 0, (it == 2) ? 1 : 0);
  }
}